// round 13
// baseline (speedup 1.0000x reference)
#include <cuda_runtime.h>
typedef unsigned long long u64;

// B=32, CIN=COUT=32, H=W=128, M1=M2=16, NMODE=32.
__device__ float2 g_Xw[1024 * 16 * 128];  // [bc][ky][h]   16 MB
__device__ float2 g_Xf[512 * 1024];       // [f][bc]        4 MB
__device__ float2 g_Yf[512 * 1024];       // [f][bo]        4 MB

// Tables for k4 (built once per launch by k0).
__device__ ulonglong2 gE3[17 * 128];  // [kt][h] {splat c, splat s}, e^{+2pi i kt h/128}
__device__ u64 gC4[16 * 32];          // [k][wp'] pair(cos*sc)  w'=2wp',2wp'+1
__device__ u64 gS4[16 * 32];          // [k][wp'] pair(sin*sc)

__device__ __forceinline__ u64 f2pack(float a, float b) {
    u64 r; asm("mov.b64 %0,{%1,%2};" : "=l"(r) : "f"(a), "f"(b)); return r;
}
__device__ __forceinline__ u64 splat(float a) {
    u64 r; asm("mov.b64 %0,{%1,%1};" : "=l"(r) : "f"(a)); return r;
}
__device__ __forceinline__ float2 f2unpack(u64 v) {
    float2 r; asm("mov.b64 {%0,%1},%2;" : "=f"(r.x), "=f"(r.y) : "l"(v)); return r;
}
__device__ __forceinline__ u64 fma2(u64 a, u64 b, u64 c) {
    u64 d; asm("fma.rn.f32x2 %0,%1,%2,%3;" : "=l"(d) : "l"(a), "l"(b), "l"(c)); return d;
}
__device__ __forceinline__ u64 add2(u64 a, u64 b) {
    u64 d; asm("add.rn.f32x2 %0,%1,%2;" : "=l"(d) : "l"(a), "l"(b)); return d;
}
__device__ __forceinline__ u64 sub2(u64 a, u64 b) {
    u64 d; asm("sub.rn.f32x2 %0,%1,%2;" : "=l"(d) : "l"(a), "l"(b)); return d;
}
__device__ __forceinline__ float2 cmul(float2 a, float2 b) {
    return make_float2(fmaf(a.x, b.x, -a.y * b.y), fmaf(a.x, b.y, a.y * b.x));
}

// ---------------- k0: k4 tables (2176 + 512 + 512 entries) ----------------
__global__ void k0_tables() {
    int id = blockIdx.x * 256 + threadIdx.x;
    float s, c;
    if (id < 2176) {                         // E3: [kt][h]
        int kt = id >> 7, h = id & 127;
        sincospif((float)(kt * h) / 64.f, &s, &c);
        ulonglong2 v; v.x = splat(c); v.y = splat(s);
        gE3[id] = v;
    } else if (id < 2688) {                  // C4
        int e = id - 2176; int k = e >> 5, wp = e & 31;
        float sc = (k ? 2.f : 1.f) / 16384.f;
        float s0, c0, s1, c1;
        sincospif((float)(k * (2 * wp))     / 64.f, &s0, &c0);
        sincospif((float)(k * (2 * wp + 1)) / 64.f, &s1, &c1);
        gC4[e] = f2pack(sc * c0, sc * c1);
    } else if (id < 3200) {                  // S4
        int e = id - 2688; int k = e >> 5, wp = e & 31;
        float sc = (k ? 2.f : 1.f) / 16384.f;
        float s0, c0, s1, c1;
        sincospif((float)(k * (2 * wp))     / 64.f, &s0, &c0);
        sincospif((float)(k * (2 * wp + 1)) / 64.f, &s1, &c1);
        gS4[e] = f2pack(sc * s0, sc * s1);
    }
}

// ---------------- k1: W-DFT (measured-good) ----------------
__global__ void __launch_bounds__(256, 4) k1_wdft(const float* __restrict__ x) {
    const int bc = blockIdx.x >> 1, half = blockIdx.x & 1;
    const int tid = threadIdx.x, ky = tid & 15, hb = tid >> 4;
    const int h0 = half * 64 + hb;
    const float4* p0 = (const float4*)x + (size_t)bc * 4096 + h0 * 32;
    const float4* p1 = p0 + 512;
    const float4* p2 = p0 + 1024;
    const float4* p3 = p0 + 1536;

    float2 tw0, tw1, tw2, tw3, s4;
    {
        float s, c;
        tw0 = make_float2(1.f, 0.f);
        sincospif(-(float)ky       / 64.f, &s, &c); tw1 = make_float2(c, s);
        sincospif(-(float)(2 * ky) / 64.f, &s, &c); tw2 = make_float2(c, s);
        sincospif(-(float)(3 * ky) / 64.f, &s, &c); tw3 = make_float2(c, s);
        sincospif(-(float)(4 * ky) / 64.f, &s, &c); s4  = make_float2(c, s);
    }
    float2 a0 = {0.f,0.f}, a1 = {0.f,0.f}, a2 = {0.f,0.f}, a3 = {0.f,0.f};
#define K1_ACC(TW, C)                                             \
    a0.x = fmaf(v0.C, TW.x, a0.x); a0.y = fmaf(v0.C, TW.y, a0.y); \
    a1.x = fmaf(v1.C, TW.x, a1.x); a1.y = fmaf(v1.C, TW.y, a1.y); \
    a2.x = fmaf(v2.C, TW.x, a2.x); a2.y = fmaf(v2.C, TW.y, a2.y); \
    a3.x = fmaf(v3.C, TW.x, a3.x); a3.y = fmaf(v3.C, TW.y, a3.y);
    #pragma unroll 2
    for (int w4 = 0; w4 < 32; w4++) {
        float4 v0 = p0[w4], v1 = p1[w4], v2 = p2[w4], v3 = p3[w4];
        K1_ACC(tw0, x) K1_ACC(tw1, y) K1_ACC(tw2, z) K1_ACC(tw3, w)
        tw0 = cmul(tw0, s4); tw1 = cmul(tw1, s4);
        tw2 = cmul(tw2, s4); tw3 = cmul(tw3, s4);
    }
#undef K1_ACC
    float2* o = g_Xw + ((size_t)bc * 16 + ky) * 128 + h0;
    o[0] = a0; o[16] = a1; o[32] = a2; o[48] = a3;
}

// ---------------- k2: H-DFT ----------------
__global__ void __launch_bounds__(256, 8) k2_hdft() {
    __shared__ float2 xw[16][130];
    const int bc = blockIdx.x, tid = threadIdx.x;
    const float2* src = g_Xw + (size_t)bc * 2048;
    for (int idx = tid; idx < 2048; idx += 256)
        xw[idx >> 7][idx & 127] = src[idx];
    __syncthreads();

    const int ky2 = tid & 7, kxi = tid >> 3;
    const int kx = (kxi < 16) ? kxi : (kxi + 96);
    float s, c;
    sincospif(-(float)kx / 64.f, &s, &c);
    const float2 st = make_float2(c, s);
    float2 t = make_float2(1.f, 0.f);
    float2 aA = {0.f,0.f}, aB = {0.f,0.f};
    #pragma unroll 4
    for (int h = 0; h < 128; h++) {
        float2 vA = xw[ky2][h], vB = xw[ky2 + 8][h];
        aA.x = fmaf(vA.x, t.x, aA.x); aA.x = fmaf(-vA.y, t.y, aA.x);
        aA.y = fmaf(vA.x, t.y, aA.y); aA.y = fmaf( vA.y, t.x, aA.y);
        aB.x = fmaf(vB.x, t.x, aB.x); aB.x = fmaf(-vB.y, t.y, aB.x);
        aB.y = fmaf(vB.x, t.y, aB.y); aB.y = fmaf( vB.y, t.x, aB.y);
        t = cmul(t, st);
    }
    g_Xf[((size_t)kxi * 16 + ky2)     * 1024 + bc] = aA;
    g_Xf[((size_t)kxi * 16 + ky2 + 8) * 1024 + bc] = aB;
}

// ---------------- k3: spectral mix ----------------
__global__ void __launch_bounds__(256, 8) k3_mix(const float* __restrict__ wr,
                                                 const float* __restrict__ wi) {
    __shared__ float2 Xs[1024], Ws[1024];
    const int f = blockIdx.x, kxi = f >> 4, kyy = f & 15;
    const int tid = threadIdx.x;
    for (int idx = tid; idx < 1024; idx += 256) {
        Xs[idx] = g_Xf[(size_t)f * 1024 + idx];
        int i = idx >> 5, o = idx & 31;
        Ws[idx] = make_float2(wr[((i * 32 + o) * 32 + kxi) * 16 + kyy],
                              wi[((i * 32 + o) * 32 + kxi) * 16 + kyy]);
    }
    __syncthreads();
    const int o = tid & 31, bg = tid >> 5;
    float2 a[4];
    #pragma unroll
    for (int j = 0; j < 4; j++) a[j] = make_float2(0.f, 0.f);
    #pragma unroll 4
    for (int i = 0; i < 32; i++) {
        float2 wv = Ws[i * 32 + o];
        #pragma unroll
        for (int j = 0; j < 4; j++) {
            float2 xv = Xs[(bg + 8 * j) * 32 + i];
            a[j].x = fmaf(xv.x, wv.x, a[j].x); a[j].x = fmaf(-xv.y, wv.y, a[j].x);
            a[j].y = fmaf(xv.x, wv.y, a[j].y); a[j].y = fmaf( xv.y, wv.x, a[j].y);
        }
    }
    #pragma unroll
    for (int j = 0; j < 4; j++)
        g_Yf[(size_t)f * 1024 + (bg + 8 * j) * 32 + o] = a[j];
}

// ---------------- k4: inverse, double-folded FFMA2. grid 1024, 68.3KB smem ----------
// smem: sE3 34816 | sC4 4096 | sS4 4096 | sYc 4096 | planes 4352 | y1T 16896
__global__ void __launch_bounds__(256, 3) k4_inv(float* __restrict__ out) {
    extern __shared__ char sm4[];
    ulonglong2* sE3 = (ulonglong2*)sm4;                 // 17*128
    u64* sC4 = (u64*)(sm4 + 34816);                     // 512
    u64* sS4 = (u64*)(sm4 + 38912);                     // 512
    float2* sYc = (float2*)(sm4 + 43008);               // 512
    u64* pl  = (u64*)(sm4 + 47104);                     // 4 planes x 136
    float* y1T = (float*)(sm4 + 51456);                 // [32][132]
    const int tid = threadIdx.x, bo = blockIdx.x;

    for (int i = tid; i < 2176; i += 256) sE3[i] = gE3[i];
    for (int i = tid; i < 512; i += 256) { sC4[i] = gC4[i]; sS4[i] = gS4[i]; }
    for (int i = tid; i < 512; i += 256) sYc[i] = g_Yf[(size_t)i * 1024 + bo];
    __syncthreads();

    // Fold kxi pairs (kt, 32-kt) into u/d planes, ky-pair packed.
    if (tid < 136) {
        const int kt = tid >> 3, kyp = tid & 7, ky0 = 2 * kyp;
        float2 a0, a1, b0, b1;
        u64 uR, uI, dR, dI;
        if (kt == 0) {
            a0 = sYc[ky0]; a1 = sYc[ky0 + 1];
            uR = f2pack(a0.x, a1.x); uI = f2pack(a0.y, a1.y);
            dR = 0ull; dI = 0ull;
        } else if (kt == 16) {
            b0 = sYc[16 * 16 + ky0]; b1 = sYc[16 * 16 + ky0 + 1];
            uR = f2pack(b0.x, b1.x);  uI = f2pack(b0.y, b1.y);
            dR = f2pack(-b0.x, -b1.x); dI = f2pack(-b0.y, -b1.y);
        } else {
            a0 = sYc[kt * 16 + ky0]; a1 = sYc[kt * 16 + ky0 + 1];
            b0 = sYc[(32 - kt) * 16 + ky0]; b1 = sYc[(32 - kt) * 16 + ky0 + 1];
            uR = f2pack(a0.x + b0.x, a1.x + b1.x);
            uI = f2pack(a0.y + b0.y, a1.y + b1.y);
            dR = f2pack(a0.x - b0.x, a1.x - b1.x);
            dI = f2pack(a0.y - b0.y, a1.y - b1.y);
        }
        pl[tid] = uR; pl[136 + tid] = uI; pl[272 + tid] = dR; pl[408 + tid] = dI;
    }
    __syncthreads();

    // Stage 1 (folded): y1[h][ky] via 17 kt terms.
    {
        const int kyp = tid & 7;
        const int h0  = 4 * (tid >> 3);
        u64 P[4] = {0,0,0,0}, Q[4] = {0,0,0,0}, R[4] = {0,0,0,0}, S_[4] = {0,0,0,0};
        #pragma unroll 4
        for (int kt = 0; kt < 17; kt++) {
            int pi = kt * 8 + kyp;
            u64 uR = pl[pi], uI = pl[136 + pi], dR = pl[272 + pi], dI = pl[408 + pi];
            #pragma unroll
            for (int hh = 0; hh < 4; hh++) {
                ulonglong2 e = sE3[kt * 128 + h0 + hh];
                P[hh]  = fma2(uR, e.x, P[hh]);
                Q[hh]  = fma2(dI, e.y, Q[hh]);
                R[hh]  = fma2(uI, e.x, R[hh]);
                S_[hh] = fma2(dR, e.y, S_[hh]);
            }
        }
        #pragma unroll
        for (int hh = 0; hh < 4; hh++) {
            float2 p = f2unpack(P[hh]), q = f2unpack(Q[hh]);
            float2 r = f2unpack(R[hh]), s = f2unpack(S_[hh]);
            int h = h0 + hh;
            y1T[(4 * kyp)     * 132 + h] = p.x - q.x;
            y1T[(4 * kyp + 1) * 132 + h] = r.x + s.x;
            y1T[(4 * kyp + 2) * 132 + h] = p.y - q.y;
            y1T[(4 * kyp + 3) * 132 + h] = r.y + s.y;
        }
    }
    __syncthreads();

    // Stage 2 (w-folded): C = sum re*cos*sc, S = sum im*sin*sc;
    // out[w'] = C - S, out[128-w'] = C + S.
    {
        const int ws = tid & 15, hg0 = tid >> 4;
        float* op = out + (size_t)bo * 16384;
        #pragma unroll
        for (int pass = 0; pass < 2; pass++) {
            const int h0 = (hg0 + 16 * pass) * 4;
            u64 C[4][2], S2[4][2];
            #pragma unroll
            for (int hi = 0; hi < 4; hi++) { C[hi][0]=C[hi][1]=S2[hi][0]=S2[hi][1]=0ull; }
            #pragma unroll 4
            for (int k = 0; k < 16; k++) {
                float4 ar = *(const float4*)(y1T + (2 * k) * 132 + h0);
                float4 ai = *(const float4*)(y1T + (2 * k + 1) * 132 + h0);
                u64 r0 = splat(ar.x), r1 = splat(ar.y), r2 = splat(ar.z), r3 = splat(ar.w);
                u64 i0 = splat(ai.x), i1 = splat(ai.y), i2 = splat(ai.z), i3 = splat(ai.w);
                #pragma unroll
                for (int m = 0; m < 2; m++) {
                    u64 ct = sC4[k * 32 + ws + 16 * m];
                    u64 st = sS4[k * 32 + ws + 16 * m];
                    C[0][m] = fma2(r0, ct, C[0][m]); S2[0][m] = fma2(i0, st, S2[0][m]);
                    C[1][m] = fma2(r1, ct, C[1][m]); S2[1][m] = fma2(i1, st, S2[1][m]);
                    C[2][m] = fma2(r2, ct, C[2][m]); S2[2][m] = fma2(i2, st, S2[2][m]);
                    C[3][m] = fma2(r3, ct, C[3][m]); S2[3][m] = fma2(i3, st, S2[3][m]);
                }
            }
            #pragma unroll
            for (int hi = 0; hi < 4; hi++) {
                float* row = op + (h0 + hi) * 128;
                #pragma unroll
                for (int m = 0; m < 2; m++) {
                    int w0 = 2 * (ws + 16 * m);
                    float2 cm = f2unpack(sub2(C[hi][m], S2[hi][m]));
                    float2 cp = f2unpack(add2(C[hi][m], S2[hi][m]));
                    row[w0]     = cm.x;
                    row[w0 + 1] = cm.y;
                    if (w0 > 0) row[128 - w0] = cp.x;
                    row[127 - w0] = cp.y;
                }
            }
        }
        // w = 64 column: out[h][64] = sum_k re_k[h] * (-1)^k * sc_k
        if (tid < 128) {
            float v = 0.f;
            #pragma unroll
            for (int k = 0; k < 16; k++) {
                float sc = (k ? 2.f : 1.f) / 16384.f;
                v = fmaf(y1T[(2 * k) * 132 + tid], (k & 1) ? -sc : sc, v);
            }
            op[tid * 128 + 64] = v;
        }
    }
}

// ---------------------------------------------------------------------------
extern "C" void kernel_launch(void* const* d_in, const int* in_sizes, int n_in,
                              void* d_out, int out_size) {
    const float* x  = (const float*)d_in[0];
    const float* wr = (const float*)d_in[1];
    const float* wi = (const float*)d_in[2];
    float* out = (float*)d_out;

    cudaFuncSetAttribute(k4_inv, cudaFuncAttributeMaxDynamicSharedMemorySize, 68352);

    k0_tables<<<13, 256>>>();
    k1_wdft<<<2048, 256>>>(x);
    k2_hdft<<<1024, 256>>>();
    k3_mix<<<512, 256>>>(wr, wi);
    k4_inv<<<1024, 256, 68352>>>(out);
}

// round 14
// speedup vs baseline: 1.7433x; 1.7433x over previous
#include <cuda_runtime.h>

// B=32, CIN=COUT=32, H=W=128, M1=M2=16, NMODE=32.
__device__ float2 g_Xw[1024 * 16 * 128];  // [bc][ky][h]   16 MB
__device__ float2 g_Xf[512 * 1024];       // [f][bc]        4 MB
__device__ float2 g_Yf[512 * 1024];       // [f][bo]        4 MB

__device__ __forceinline__ float2 cmul(float2 a, float2 b) {
    return make_float2(fmaf(a.x, b.x, -a.y * b.y), fmaf(a.x, b.y, a.y * b.x));
}

// ---------------- k1: W-DFT (R2, measured-good) ----------------
__global__ void __launch_bounds__(256, 4) k1_wdft(const float* __restrict__ x) {
    const int bc = blockIdx.x >> 1, half = blockIdx.x & 1;
    const int tid = threadIdx.x, ky = tid & 15, hb = tid >> 4;
    const int h0 = half * 64 + hb;
    const float4* p0 = (const float4*)x + (size_t)bc * 4096 + h0 * 32;
    const float4* p1 = p0 + 512;
    const float4* p2 = p0 + 1024;
    const float4* p3 = p0 + 1536;

    float2 tw0, tw1, tw2, tw3, s4;
    {
        float s, c;
        tw0 = make_float2(1.f, 0.f);
        sincospif(-(float)ky       / 64.f, &s, &c); tw1 = make_float2(c, s);
        sincospif(-(float)(2 * ky) / 64.f, &s, &c); tw2 = make_float2(c, s);
        sincospif(-(float)(3 * ky) / 64.f, &s, &c); tw3 = make_float2(c, s);
        sincospif(-(float)(4 * ky) / 64.f, &s, &c); s4  = make_float2(c, s);
    }
    float2 a0 = {0.f,0.f}, a1 = {0.f,0.f}, a2 = {0.f,0.f}, a3 = {0.f,0.f};
#define K1_ACC(TW, C)                                             \
    a0.x = fmaf(v0.C, TW.x, a0.x); a0.y = fmaf(v0.C, TW.y, a0.y); \
    a1.x = fmaf(v1.C, TW.x, a1.x); a1.y = fmaf(v1.C, TW.y, a1.y); \
    a2.x = fmaf(v2.C, TW.x, a2.x); a2.y = fmaf(v2.C, TW.y, a2.y); \
    a3.x = fmaf(v3.C, TW.x, a3.x); a3.y = fmaf(v3.C, TW.y, a3.y);
    #pragma unroll 2
    for (int w4 = 0; w4 < 32; w4++) {
        float4 v0 = p0[w4], v1 = p1[w4], v2 = p2[w4], v3 = p3[w4];
        K1_ACC(tw0, x) K1_ACC(tw1, y) K1_ACC(tw2, z) K1_ACC(tw3, w)
        tw0 = cmul(tw0, s4); tw1 = cmul(tw1, s4);
        tw2 = cmul(tw2, s4); tw3 = cmul(tw3, s4);
    }
#undef K1_ACC
    float2* o = g_Xw + ((size_t)bc * 16 + ky) * 128 + h0;
    o[0] = a0; o[16] = a1; o[32] = a2; o[48] = a3;
}

// ---------------- k2: H-DFT (R2) ----------------
__global__ void __launch_bounds__(256, 8) k2_hdft() {
    __shared__ float2 xw[16][130];
    const int bc = blockIdx.x, tid = threadIdx.x;
    const float2* src = g_Xw + (size_t)bc * 2048;
    for (int idx = tid; idx < 2048; idx += 256)
        xw[idx >> 7][idx & 127] = src[idx];
    __syncthreads();

    const int ky2 = tid & 7, kxi = tid >> 3;
    const int kx = (kxi < 16) ? kxi : (kxi + 96);
    float s, c;
    sincospif(-(float)kx / 64.f, &s, &c);
    const float2 st = make_float2(c, s);
    float2 t = make_float2(1.f, 0.f);
    float2 aA = {0.f,0.f}, aB = {0.f,0.f};
    #pragma unroll 4
    for (int h = 0; h < 128; h++) {
        float2 vA = xw[ky2][h], vB = xw[ky2 + 8][h];
        aA.x = fmaf(vA.x, t.x, aA.x); aA.x = fmaf(-vA.y, t.y, aA.x);
        aA.y = fmaf(vA.x, t.y, aA.y); aA.y = fmaf( vA.y, t.x, aA.y);
        aB.x = fmaf(vB.x, t.x, aB.x); aB.x = fmaf(-vB.y, t.y, aB.x);
        aB.y = fmaf(vB.x, t.y, aB.y); aB.y = fmaf( vB.y, t.x, aB.y);
        t = cmul(t, st);
    }
    g_Xf[((size_t)kxi * 16 + ky2)     * 1024 + bc] = aA;
    g_Xf[((size_t)kxi * 16 + ky2 + 8) * 1024 + bc] = aB;
}

// ---------------- k3: spectral mix (R2) ----------------
__global__ void __launch_bounds__(256, 8) k3_mix(const float* __restrict__ wr,
                                                 const float* __restrict__ wi) {
    __shared__ float2 Xs[1024], Ws[1024];
    const int f = blockIdx.x, kxi = f >> 4, kyy = f & 15;
    const int tid = threadIdx.x;
    for (int idx = tid; idx < 1024; idx += 256) {
        Xs[idx] = g_Xf[(size_t)f * 1024 + idx];
        int i = idx >> 5, o = idx & 31;
        int widx = ((i * 32 + o) * 32 + kxi) * 16 + kyy;
        Ws[idx] = make_float2(wr[widx], wi[widx]);
    }
    __syncthreads();
    const int o = tid & 31, bg = tid >> 5;
    float2 a[4];
    #pragma unroll
    for (int j = 0; j < 4; j++) a[j] = make_float2(0.f, 0.f);
    #pragma unroll 4
    for (int i = 0; i < 32; i++) {
        float2 wv = Ws[i * 32 + o];
        #pragma unroll
        for (int j = 0; j < 4; j++) {
            float2 xv = Xs[(bg + 8 * j) * 32 + i];
            a[j].x = fmaf(xv.x, wv.x, a[j].x); a[j].x = fmaf(-xv.y, wv.y, a[j].x);
            a[j].y = fmaf(xv.x, wv.y, a[j].y); a[j].y = fmaf( xv.y, wv.x, a[j].y);
        }
    }
    #pragma unroll
    for (int j = 0; j < 4; j++)
        g_Yf[(size_t)f * 1024 + (bg + 8 * j) * 32 + o] = a[j];
}

// ---------------- k4: inverse (R2 skeleton + kxi-fold + w-fold) ----------------
// Stage 1 (folded): y1[h][ky] = Y0 + sum_{kt=1..15}(u cos + i d sin) + Y16 e^{-i16θ}
// Stage 2 (w-folded): C - S at w', C + S at 128-w'.
__global__ void __launch_bounds__(256) k4_inv(float* __restrict__ out) {
    __shared__ float2 Ys[512];       // [kxi][ky]
    __shared__ float2 y1[2048];      // [h][ky]
    const int bo = blockIdx.x, tid = threadIdx.x;

    for (int idx = tid; idx < 512; idx += 256)
        Ys[idx] = g_Yf[(size_t)idx * 1024 + bo];
    __syncthreads();

    // Stage 1: thread (ky, hb) owns h = hb + 16j, j<8. 8 twiddle chains (e^{+i h theta}),
    // folded over kt: 17 iterations instead of 32.
    {
        const int ky = tid & 15;
        const int hb = tid >> 4;
        float2 stp[8], tw[8], acc[8];
        #pragma unroll
        for (int j = 0; j < 8; j++) {
            float s, c;
            sincospif((float)(hb + 16 * j) / 64.f, &s, &c);
            stp[j] = make_float2(c, s);
            tw[j]  = make_float2(1.f, 0.f);
            acc[j] = make_float2(0.f, 0.f);
        }
        #pragma unroll 4
        for (int kt = 0; kt <= 16; kt++) {
            float uR, uI, dR, dI;
            if (kt == 0) {
                float2 Y0 = Ys[ky];
                uR = Y0.x; uI = Y0.y; dR = 0.f; dI = 0.f;
            } else if (kt == 16) {
                float2 Y16 = Ys[256 + ky];
                uR = Y16.x; uI = Y16.y; dR = -Y16.x; dI = -Y16.y;
            } else {
                float2 Ya = Ys[kt * 16 + ky];
                float2 Yb = Ys[(32 - kt) * 16 + ky];
                uR = Ya.x + Yb.x; uI = Ya.y + Yb.y;
                dR = Ya.x - Yb.x; dI = Ya.y - Yb.y;
            }
            #pragma unroll
            for (int j = 0; j < 8; j++) {
                acc[j].x = fmaf(uR, tw[j].x, acc[j].x);
                acc[j].x = fmaf(-dI, tw[j].y, acc[j].x);
                acc[j].y = fmaf(uI, tw[j].x, acc[j].y);
                acc[j].y = fmaf(dR, tw[j].y, acc[j].y);
                tw[j] = cmul(tw[j], stp[j]);
            }
        }
        #pragma unroll
        for (int j = 0; j < 8; j++) y1[(hb + 16 * j) * 16 + ky] = acc[j];
    }
    __syncthreads();

    // Stage 2: thread (w' = tid&63, hq = tid>>6) covers rows h = hq + 4j, j<32,
    // columns w' and 128-w'. Hoisted register twiddles with scale folded in.
    {
        const float inv = 1.0f / 16384.0f;
        const int wp = tid & 63;           // w' 0..63
        const int hq = tid >> 6;           // 0..3
        float twr[16], twi[15];
        #pragma unroll
        for (int k = 0; k < 16; k++) {
            float s, c;
            sincospif((float)(k * wp) / 64.f, &s, &c);
            float sc = (k == 0) ? inv : 2.0f * inv;
            twr[k] = c * sc;
            if (k >= 1) twi[k - 1] = s * sc;
        }
        float* op = out + (size_t)bo * 16384;
        #pragma unroll 2
        for (int j = 0; j < 32; j++) {
            int h = hq + 4 * j;
            const float4* r = (const float4*)(y1 + h * 16);
            float4 r0 = r[0];
            float C = r0.x * twr[0];               // k=0 (re)
            C = fmaf(r0.z, twr[1], C);             // k=1 re
            float S = r0.w * twi[0];               // k=1 im
            #pragma unroll
            for (int m = 1; m < 8; m++) {
                float4 rm = r[m];
                C = fmaf(rm.x, twr[2 * m],     C);     // k=2m   re
                S = fmaf(rm.y, twi[2 * m - 1], S);     // k=2m   im
                C = fmaf(rm.z, twr[2 * m + 1], C);     // k=2m+1 re
                S = fmaf(rm.w, twi[2 * m],     S);     // k=2m+1 im
            }
            float* row = op + h * 128;
            row[wp] = C - S;
            if (wp > 0) row[128 - wp] = C + S;
        }
        // w = 64 column: out[h][64] = sum_k re_k * (-1)^k * sc_k
        if (tid < 128) {
            const float4* r = (const float4*)(y1 + tid * 16);
            float v = 0.f;
            #pragma unroll
            for (int m = 0; m < 8; m++) {
                float4 rm = r[m];
                float sA = (m == 0) ? inv : 2.0f * inv;   // k=2m even -> +
                v = fmaf(rm.x,  sA, v);
                v = fmaf(rm.z, -2.0f * inv, v);           // k=2m+1 odd -> -
            }
            op[tid * 128 + 64] = v;
        }
    }
}

// ---------------------------------------------------------------------------
extern "C" void kernel_launch(void* const* d_in, const int* in_sizes, int n_in,
                              void* d_out, int out_size) {
    const float* x  = (const float*)d_in[0];
    const float* wr = (const float*)d_in[1];
    const float* wi = (const float*)d_in[2];
    float* out = (float*)d_out;

    k1_wdft<<<2048, 256>>>(x);
    k2_hdft<<<1024, 256>>>();
    k3_mix<<<512, 256>>>(wr, wi);
    k4_inv<<<1024, 256>>>(out);
}

// round 16
// speedup vs baseline: 1.9344x; 1.1096x over previous
#include <cuda_runtime.h>
typedef unsigned long long u64;

// B=32, CIN=COUT=32, H=W=128, M1=M2=16, NMODE=32.
__device__ float2 g_Xw[1024 * 16 * 128];  // [bc][ky][h]   16 MB
__device__ float2 g_Xf[512 * 1024];       // [f][bc]        4 MB
__device__ float2 g_Yf[512 * 1024];       // [f][bo]        4 MB

__device__ __forceinline__ float2 cmul(float2 a, float2 b) {
    return make_float2(fmaf(a.x, b.x, -a.y * b.y), fmaf(a.x, b.y, a.y * b.x));
}
__device__ __forceinline__ u64 f2pack(float a, float b) {
    u64 r; asm("mov.b64 %0,{%1,%2};" : "=l"(r) : "f"(a), "f"(b)); return r;
}
__device__ __forceinline__ u64 splat(float a) {
    u64 r; asm("mov.b64 %0,{%1,%1};" : "=l"(r) : "f"(a)); return r;
}
__device__ __forceinline__ float2 f2unpack(u64 v) {
    float2 r; asm("mov.b64 {%0,%1},%2;" : "=f"(r.x), "=f"(r.y) : "l"(v)); return r;
}
__device__ __forceinline__ u64 fma2(u64 a, u64 b, u64 c) {
    u64 d; asm("fma.rn.f32x2 %0,%1,%2,%3;" : "=l"(d) : "l"(a), "l"(b), "l"(c)); return d;
}
__device__ __forceinline__ u64 mul2(u64 a, u64 b) {
    u64 d; asm("mul.rn.f32x2 %0,%1,%2;" : "=l"(d) : "l"(a), "l"(b)); return d;
}

// ---------------- k1: W-DFT, fma2 over ky-pairs, register twiddles ----------------
// grid 1024 (bc), block 256 = 8 kyp x 32 hb; thread: 4 rows (hb+32j) x 2 ky.
__global__ void __launch_bounds__(256) k1_wdft(const float* __restrict__ x) {
    const int bc = blockIdx.x, tid = threadIdx.x;
    const int kyp = tid & 7, hb = tid >> 3;
    const int ky0 = 2 * kyp, ky1 = ky0 + 1;

    u64 c2[4], s2[4];
    #pragma unroll
    for (int c = 0; c < 4; c++) {
        float s0, cc0, s1, cc1;
        sincospif((float)(ky0 * c) / 64.f, &s0, &cc0);
        sincospif((float)(ky1 * c) / 64.f, &s1, &cc1);
        c2[c] = f2pack(cc0, cc1); s2[c] = f2pack(-s0, -s1);
    }
    float sA, cA, sB, cB;
    sincospif((float)(ky0 * 4) / 64.f, &sA, &cA);
    sincospif((float)(ky1 * 4) / 64.f, &sB, &cB);
    const u64 C4 = f2pack(cA, cB), S4 = f2pack(-sA, -sB), NS4 = f2pack(sA, sB);

    u64 re[4] = {0,0,0,0}, im[4] = {0,0,0,0};
    const float4* xp = (const float4*)(x + (size_t)bc * 16384);

    #pragma unroll 2
    for (int w4 = 0; w4 < 32; w4++) {
        float4 v0 = xp[hb * 32 + w4];
        float4 v1 = xp[(hb + 32) * 32 + w4];
        float4 v2 = xp[(hb + 64) * 32 + w4];
        float4 v3 = xp[(hb + 96) * 32 + w4];
#define K1S(c, comp) { \
        u64 x0 = splat(v0.comp), x1 = splat(v1.comp), x2 = splat(v2.comp), x3 = splat(v3.comp); \
        re[0] = fma2(x0, c2[c], re[0]); im[0] = fma2(x0, s2[c], im[0]); \
        re[1] = fma2(x1, c2[c], re[1]); im[1] = fma2(x1, s2[c], im[1]); \
        re[2] = fma2(x2, c2[c], re[2]); im[2] = fma2(x2, s2[c], im[2]); \
        re[3] = fma2(x3, c2[c], re[3]); im[3] = fma2(x3, s2[c], im[3]); }
        K1S(0, x) K1S(1, y) K1S(2, z) K1S(3, w)
#undef K1S
        #pragma unroll
        for (int c = 0; c < 4; c++) {
            u64 nc = fma2(s2[c], NS4, mul2(c2[c], C4));
            u64 ns = fma2(s2[c], C4,  mul2(c2[c], S4));
            c2[c] = nc; s2[c] = ns;
        }
    }
    #pragma unroll
    for (int j = 0; j < 4; j++) {
        int h = hb + 32 * j;
        float2 R = f2unpack(re[j]), I = f2unpack(im[j]);
        g_Xw[((size_t)bc * 16 + ky0) * 128 + h] = make_float2(R.x, I.x);
        g_Xw[((size_t)bc * 16 + ky1) * 128 + h] = make_float2(R.y, I.y);
    }
}

// ---------------- k2: H-DFT with kx<->-kx fold (P/Q/R/S) ----------------
// grid 1024 (bc), block 256 = 16 groups x 16 ky. Group g>=1: outputs kxi=g and 32-g.
// Group 0: outputs kxi=0 (plain sum) and kxi=16 (kt=16 chain).
__global__ void __launch_bounds__(256, 8) k2_hdft() {
    __shared__ float2 xw[16][129];
    const int bc = blockIdx.x, tid = threadIdx.x;
    const float2* src = g_Xw + (size_t)bc * 2048;
    for (int idx = tid; idx < 2048; idx += 256)
        xw[idx >> 7][idx & 127] = src[idx];
    __syncthreads();

    const int ky = tid & 15, g = tid >> 4;
    const int kt = (g == 0) ? 16 : g;
    float S, C;
    sincospif((float)kt / 64.f, &S, &C);
    const float2 st = make_float2(C, S);
    float2 t = make_float2(1.f, 0.f);
    float P = 0.f, Q = 0.f, R = 0.f, S_ = 0.f, zR = 0.f, zI = 0.f;

    #pragma unroll 4
    for (int h = 0; h < 128; h++) {
        float2 V = xw[ky][h];
        P  = fmaf(V.x, t.x, P);  Q  = fmaf(V.y, t.y, Q);
        R  = fmaf(V.y, t.x, R);  S_ = fmaf(V.x, t.y, S_);
        if (g == 0) { zR += V.x; zI += V.y; }
        t = cmul(t, st);
    }
    if (g == 0) {
        g_Xf[(size_t)ky * 1024 + bc]              = make_float2(zR, zI);
        g_Xf[(size_t)(256 + ky) * 1024 + bc]      = make_float2(P - Q, R + S_);
    } else {
        g_Xf[(size_t)(kt * 16 + ky) * 1024 + bc]        = make_float2(P + Q, R - S_);
        g_Xf[(size_t)((32 - kt) * 16 + ky) * 1024 + bc] = make_float2(P - Q, R + S_);
    }
}

// ---------------- k3: spectral mix (R2, unchanged) ----------------
__global__ void __launch_bounds__(256, 8) k3_mix(const float* __restrict__ wr,
                                                 const float* __restrict__ wi) {
    __shared__ float2 Xs[1024], Ws[1024];
    const int f = blockIdx.x, kxi = f >> 4, kyy = f & 15;
    const int tid = threadIdx.x;
    for (int idx = tid; idx < 1024; idx += 256) {
        Xs[idx] = g_Xf[(size_t)f * 1024 + idx];
        int i = idx >> 5, o = idx & 31;
        int widx = ((i * 32 + o) * 32 + kxi) * 16 + kyy;
        Ws[idx] = make_float2(wr[widx], wi[widx]);
    }
    __syncthreads();
    const int o = tid & 31, bg = tid >> 5;
    float2 a[4];
    #pragma unroll
    for (int j = 0; j < 4; j++) a[j] = make_float2(0.f, 0.f);
    #pragma unroll 4
    for (int i = 0; i < 32; i++) {
        float2 wv = Ws[i * 32 + o];
        #pragma unroll
        for (int j = 0; j < 4; j++) {
            float2 xv = Xs[(bg + 8 * j) * 32 + i];
            a[j].x = fmaf(xv.x, wv.x, a[j].x); a[j].x = fmaf(-xv.y, wv.y, a[j].x);
            a[j].y = fmaf(xv.x, wv.y, a[j].y); a[j].y = fmaf( xv.y, wv.x, a[j].y);
        }
    }
    #pragma unroll
    for (int j = 0; j < 4; j++)
        g_Yf[(size_t)f * 1024 + (bg + 8 * j) * 32 + o] = a[j];
}

// ---------------- k4: inverse (R14, unchanged) ----------------
__global__ void __launch_bounds__(256) k4_inv(float* __restrict__ out) {
    __shared__ float2 Ys[512];
    __shared__ float2 y1[2048];
    const int bo = blockIdx.x, tid = threadIdx.x;

    for (int idx = tid; idx < 512; idx += 256)
        Ys[idx] = g_Yf[(size_t)idx * 1024 + bo];
    __syncthreads();

    {
        const int ky = tid & 15;
        const int hb = tid >> 4;
        float2 stp[8], tw[8], acc[8];
        #pragma unroll
        for (int j = 0; j < 8; j++) {
            float s, c;
            sincospif((float)(hb + 16 * j) / 64.f, &s, &c);
            stp[j] = make_float2(c, s);
            tw[j]  = make_float2(1.f, 0.f);
            acc[j] = make_float2(0.f, 0.f);
        }
        #pragma unroll 4
        for (int kt = 0; kt <= 16; kt++) {
            float uR, uI, dR, dI;
            if (kt == 0) {
                float2 Y0 = Ys[ky];
                uR = Y0.x; uI = Y0.y; dR = 0.f; dI = 0.f;
            } else if (kt == 16) {
                float2 Y16 = Ys[256 + ky];
                uR = Y16.x; uI = Y16.y; dR = -Y16.x; dI = -Y16.y;
            } else {
                float2 Ya = Ys[kt * 16 + ky];
                float2 Yb = Ys[(32 - kt) * 16 + ky];
                uR = Ya.x + Yb.x; uI = Ya.y + Yb.y;
                dR = Ya.x - Yb.x; dI = Ya.y - Yb.y;
            }
            #pragma unroll
            for (int j = 0; j < 8; j++) {
                acc[j].x = fmaf(uR, tw[j].x, acc[j].x);
                acc[j].x = fmaf(-dI, tw[j].y, acc[j].x);
                acc[j].y = fmaf(uI, tw[j].x, acc[j].y);
                acc[j].y = fmaf(dR, tw[j].y, acc[j].y);
                tw[j] = cmul(tw[j], stp[j]);
            }
        }
        #pragma unroll
        for (int j = 0; j < 8; j++) y1[(hb + 16 * j) * 16 + ky] = acc[j];
    }
    __syncthreads();

    {
        const float inv = 1.0f / 16384.0f;
        const int wp = tid & 63;
        const int hq = tid >> 6;
        float twr[16], twi[15];
        #pragma unroll
        for (int k = 0; k < 16; k++) {
            float s, c;
            sincospif((float)(k * wp) / 64.f, &s, &c);
            float sc = (k == 0) ? inv : 2.0f * inv;
            twr[k] = c * sc;
            if (k >= 1) twi[k - 1] = s * sc;
        }
        float* op = out + (size_t)bo * 16384;
        #pragma unroll 2
        for (int j = 0; j < 32; j++) {
            int h = hq + 4 * j;
            const float4* r = (const float4*)(y1 + h * 16);
            float4 r0 = r[0];
            float C = r0.x * twr[0];
            C = fmaf(r0.z, twr[1], C);
            float S = r0.w * twi[0];
            #pragma unroll
            for (int m = 1; m < 8; m++) {
                float4 rm = r[m];
                C = fmaf(rm.x, twr[2 * m],     C);
                S = fmaf(rm.y, twi[2 * m - 1], S);
                C = fmaf(rm.z, twr[2 * m + 1], C);
                S = fmaf(rm.w, twi[2 * m],     S);
            }
            float* row = op + h * 128;
            row[wp] = C - S;
            if (wp > 0) row[128 - wp] = C + S;
        }
        if (tid < 128) {
            const float4* r = (const float4*)(y1 + tid * 16);
            float v = 0.f;
            #pragma unroll
            for (int m = 0; m < 8; m++) {
                float4 rm = r[m];
                float sA = (m == 0) ? inv : 2.0f * inv;
                v = fmaf(rm.x,  sA, v);
                v = fmaf(rm.z, -2.0f * inv, v);
            }
            op[tid * 128 + 64] = v;
        }
    }
}

// ---------------------------------------------------------------------------
extern "C" void kernel_launch(void* const* d_in, const int* in_sizes, int n_in,
                              void* d_out, int out_size) {
    const float* x  = (const float*)d_in[0];
    const float* wr = (const float*)d_in[1];
    const float* wi = (const float*)d_in[2];
    float* out = (float*)d_out;

    k1_wdft<<<1024, 256>>>(x);
    k2_hdft<<<1024, 256>>>();
    k3_mix<<<512, 256>>>(wr, wi);
    k4_inv<<<1024, 256>>>(out);
}